// round 11
// baseline (speedup 1.0000x reference)
#include <cuda_runtime.h>
#include <cuda_fp16.h>
#include <cstdint>
#include <cstddef>

#define NR 8192
#define MR 8192
#define HD 512

// ---------------- scratch (device globals: allowed) ----------------
__device__ __align__(128) __half g_fh[(size_t)NR * HD], g_fl[(size_t)NR * HD];
__device__ __align__(128) __half g_mh[(size_t)MR * HD], g_ml[(size_t)MR * HD];
__device__ __align__(128) __half g_t1h[HD * HD], g_t1l[HD * HD];
__device__ __align__(128) float  g_c[HD];
__device__ __align__(128) __half g_qh[(size_t)NR * HD], g_ql[(size_t)NR * HD];
__device__ __align__(128) __half g_mth[(size_t)HD * MR];
__device__ __align__(128) float  g_s[(size_t)NR * MR];
__device__ __align__(128) __half g_ph[(size_t)NR * MR];

// ---------------- helpers ----------------
__device__ __forceinline__ uint32_t smem_u32(const void* p) {
    uint32_t a;
    asm("{ .reg .u64 t; cvta.to.shared.u64 t, %1; cvt.u32.u64 %0, t; }" : "=r"(a) : "l"(p));
    return a;
}
__device__ __forceinline__ void cp16(uint32_t dst, const void* src) {
    asm volatile("cp.async.cg.shared.global [%0], [%1], 16;" :: "r"(dst), "l"(src));
}
__device__ __forceinline__ void ldsm4(uint32_t* r, uint32_t addr) {
    asm volatile("ldmatrix.sync.aligned.m8n8.x4.shared.b16 {%0,%1,%2,%3}, [%4];"
        : "=r"(r[0]), "=r"(r[1]), "=r"(r[2]), "=r"(r[3]) : "r"(addr));
}
__device__ __forceinline__ void mma16816(float* c, const uint32_t* a, const uint32_t* b) {
    asm volatile("mma.sync.aligned.m16n8k16.row.col.f32.f16.f16.f32 "
        "{%0,%1,%2,%3}, {%4,%5,%6,%7}, {%8,%9}, {%0,%1,%2,%3};"
        : "+f"(c[0]), "+f"(c[1]), "+f"(c[2]), "+f"(c[3])
        : "r"(a[0]), "r"(a[1]), "r"(a[2]), "r"(a[3]), "r"(b[0]), "r"(b[1]));
}
__device__ __forceinline__ void split1(float v, __half& h, __half& l) {
    h = __float2half_rn(v);
    l = __float2half_rn(v - __half2float(h));
}
__device__ __forceinline__ uint32_t pack2(__half a, __half b) {
    __half2 t = __halves2half2(a, b);
    return *(uint32_t*)&t;
}

// smem pitches: KC=32 -> 80B rows; KC=64 -> 144B rows. Both conflict-free for
// ldmatrix (row phase stride 4 banks) and 16B-aligned for cp.async.
template <int KC> struct TileCfg;
template <> struct TileCfg<32> { static constexpr int PITCH = 80;  };
template <> struct TileCfg<64> { static constexpr int PITCH = 144; };

// ---------------- elementwise fp32 -> (hi, lo) fp16 ----------------
__global__ __launch_bounds__(256)
void split_kernel(const float* __restrict__ s, __half* __restrict__ dh,
                  __half* __restrict__ dl, size_t n4)
{
    size_t i = (size_t)blockIdx.x * blockDim.x + threadIdx.x;
    if (i >= n4) return;
    float4 v = ((const float4*)s)[i];
    __half hx, lx, hy, ly, hz, lz, hw, lw;
    split1(v.x, hx, lx); split1(v.y, hy, ly);
    split1(v.z, hz, lz); split1(v.w, hw, lw);
    ((uint2*)dh)[i] = make_uint2(pack2(hx, hy), pack2(hz, hw));
    ((uint2*)dl)[i] = make_uint2(pack2(lx, ly), pack2(lz, lw));
}

// ---------------- T1 = Wk^T @ Wq (fp32), split-fp16 output ----------------
__global__ __launch_bounds__(256)
void wprod_kernel(const float* __restrict__ Wk, const float* __restrict__ Wq,
                  __half* __restrict__ Th, __half* __restrict__ Tl)
{
    __shared__ float Ks[16][17], Qs[16][17];
    const int i0 = blockIdx.x * 16;
    const int j0 = blockIdx.y * 16;
    const int tx = threadIdx.x & 15;
    const int ty = threadIdx.x >> 4;
    float acc = 0.f;
    for (int t0 = 0; t0 < HD; t0 += 16) {
        Ks[ty][tx] = Wk[(t0 + ty) * HD + i0 + tx];
        Qs[ty][tx] = Wq[(t0 + ty) * HD + j0 + tx];
        __syncthreads();
#pragma unroll
        for (int t = 0; t < 16; ++t)
            acc = fmaf(Ks[t][ty], Qs[t][tx], acc);
        __syncthreads();
    }
    __half h, l; split1(acc, h, l);
    Th[(size_t)(i0 + ty) * HD + j0 + tx] = h;
    Tl[(size_t)(i0 + ty) * HD + j0 + tx] = l;
}

// ---------------- c = bq @ Wk, parallel ----------------
__global__ __launch_bounds__(256)
void cvec_kernel(const float* __restrict__ bq, const float* __restrict__ Wk,
                 float* __restrict__ c)
{
    __shared__ float sm[4][64];
    const int tid = threadIdx.x;
    const int j = blockIdx.x * 64 + (tid & 63);
    const int ts = (tid >> 6) * 128;
    float a = 0.f;
#pragma unroll 4
    for (int t = ts; t < ts + 128; ++t) a = fmaf(bq[t], Wk[t * HD + j], a);
    sm[tid >> 6][tid & 63] = a;
    __syncthreads();
    if (tid < 64)
        c[blockIdx.x * 64 + tid] = (sm[0][tid] + sm[1][tid]) + (sm[2][tid] + sm[3][tid]);
}

// ---------------- mem [MR][HD] fp32 -> memT [HD][MR] fp16 (hi only) ----------------
__global__ __launch_bounds__(256)
void transpose_h(const float* __restrict__ src, __half* __restrict__ dh)
{
    __shared__ float t[32][33];
    const int j0 = blockIdx.x * 32;
    const int h0 = blockIdx.y * 32;
    const int tx = threadIdx.x & 31;
    const int ty = threadIdx.x >> 5;
#pragma unroll
    for (int i = 0; i < 4; ++i)
        t[ty + i * 8][tx] = src[(size_t)(j0 + ty + i * 8) * HD + h0 + tx];
    __syncthreads();
#pragma unroll
    for (int i = 0; i < 4; ++i) {
        size_t o = (size_t)(h0 + ty + i * 8) * MR + j0 + tx;
        dh[o] = __float2half_rn(t[tx][ty + i * 8]);
    }
}

// ---------------------------------------------------------------------------
// NT GEMM via mma.sync, fp32 accumulate. FAT-WARP layout:
// CTA 128x128, 128 threads, 4 warps 2x2, warp tile 64x64 (128 accum regs/thr).
// NPASS==3: D = Ah*Bh + Ah*Bl + Al*Bh   (stage mats: Ah,Bh,Bl,Al)
// NPASS==1: D = Ah*Bh                   (stage mats: Ah,Bh)
// KC: K-chunk (32 or 64); NSTG-stage cp.async pipeline, 2 CTAs/SM.
// EPI: 0 = +bias[n], split fp16 out; 1 = fp32 out; 2 = 0.5*F + 0.5*acc (F=biasF)
// ---------------------------------------------------------------------------
template <int EPI, int NPASS, int NSTG, int KC>
__global__ __launch_bounds__(128, 2)
void mma_gemm(const __half* __restrict__ Ah, const __half* __restrict__ Al,
              const __half* __restrict__ Bh, const __half* __restrict__ Bl,
              const float* __restrict__ biasF,
              float* __restrict__ outf,
              __half* __restrict__ outh, __half* __restrict__ outl,
              int M, int N, int K)
{
    constexpr int PITCH = TileCfg<KC>::PITCH;
    constexpr uint32_t MATB = 128 * PITCH;
    constexpr int NMAT = (NPASS == 3) ? 4 : 2;
    constexpr uint32_t STAGE = NMAT * MATB;
    constexpr int CPT = KC / 8;          // 16B chunks per row
    constexpr int NITER = 128 * CPT / 128;  // cp16 per mat per thread

    extern __shared__ char smem[];
    const uint32_t sbase = smem_u32(smem);
    const int tid = threadIdx.x;
    const int wid = tid >> 5;
    const int lane = tid & 31;
    const int bm = blockIdx.y * 128;
    const int bn = blockIdx.x * 128;
    const int wm = (wid & 1) * 64;
    const int wn = (wid >> 1) * 64;

    const int NC = K / KC;

    auto loadc = [&](int c) {
        const uint32_t sb = sbase + (uint32_t)(c % NSTG) * STAGE;
        const int k0 = c * KC;
#pragma unroll
        for (int i = 0; i < NITER; ++i) {
            const int idx = tid + i * 128;
            const int r = idx / CPT;
            const int ch = (idx % CPT) * 16;
            cp16(sb + r * PITCH + ch,        Ah + (size_t)(bm + r) * K + k0 + ch / 2);
            cp16(sb + MATB + r * PITCH + ch, Bh + (size_t)(bn + r) * K + k0 + ch / 2);
            if (NPASS == 3) {
                cp16(sb + 2 * MATB + r * PITCH + ch, Bl + (size_t)(bn + r) * K + k0 + ch / 2);
                cp16(sb + 3 * MATB + r * PITCH + ch, Al + (size_t)(bm + r) * K + k0 + ch / 2);
            }
        }
    };

    float acc[4][8][4];
#pragma unroll
    for (int mg = 0; mg < 4; ++mg)
#pragma unroll
        for (int ng = 0; ng < 8; ++ng)
#pragma unroll
            for (int j = 0; j < 4; ++j) acc[mg][ng][j] = 0.f;

    const uint32_t aRow = (lane & 15);
    const uint32_t aChk = (lane >> 4);
    const uint32_t bRow = ((lane >> 4) & 1) * 8 + (lane & 7);
    const uint32_t bChk = (lane >> 3) & 1;

    auto compute = [&](int c) {
        const uint32_t st = sbase + (uint32_t)(c % NSTG) * STAGE;
#pragma unroll
        for (int ks = 0; ks < KC / 16; ++ks) {
            uint32_t ah[4][4], al[4][4];
#pragma unroll
            for (int mg = 0; mg < 4; ++mg) {
                uint32_t off = (wm + mg * 16 + aRow) * PITCH + aChk * 16 + ks * 32;
                ldsm4(ah[mg], st + off);
                if (NPASS == 3) ldsm4(al[mg], st + 3 * MATB + off);
            }
#pragma unroll
            for (int ph = 0; ph < 2; ++ph) {
                uint32_t bh[2][4], bl[2][4];
#pragma unroll
                for (int p2 = 0; p2 < 2; ++p2) {
                    uint32_t off = (wn + (ph * 2 + p2) * 16 + bRow) * PITCH + bChk * 16 + ks * 32;
                    ldsm4(bh[p2], st + MATB + off);
                    if (NPASS == 3) ldsm4(bl[p2], st + 2 * MATB + off);
                }
#pragma unroll
                for (int p2 = 0; p2 < 2; ++p2)
#pragma unroll
                    for (int mg = 0; mg < 4; ++mg) {
                        const int ng = 2 * (ph * 2 + p2);
                        mma16816(acc[mg][ng + 0], ah[mg], bh[p2] + 0);
                        mma16816(acc[mg][ng + 1], ah[mg], bh[p2] + 2);
                    }
                if (NPASS == 3) {
#pragma unroll
                    for (int p2 = 0; p2 < 2; ++p2)
#pragma unroll
                        for (int mg = 0; mg < 4; ++mg) {
                            const int ng = 2 * (ph * 2 + p2);
                            mma16816(acc[mg][ng + 0], ah[mg], bl[p2] + 0);
                            mma16816(acc[mg][ng + 1], ah[mg], bl[p2] + 2);
                        }
#pragma unroll
                    for (int p2 = 0; p2 < 2; ++p2)
#pragma unroll
                        for (int mg = 0; mg < 4; ++mg) {
                            const int ng = 2 * (ph * 2 + p2);
                            mma16816(acc[mg][ng + 0], al[mg], bh[p2] + 0);
                            mma16816(acc[mg][ng + 1], al[mg], bh[p2] + 2);
                        }
                }
            }
        }
    };

    // pipeline: wait(chunk c) -> sync -> prefetch(c+NSTG-1) -> compute(c)
#pragma unroll 1
    for (int c = 0; c < NSTG - 1 && c < NC; ++c) {
        loadc(c);
        asm volatile("cp.async.commit_group;" ::: "memory");
    }
#pragma unroll 1
    for (int c = 0; c < NC; ++c) {
        if (NSTG >= 3 && c + 1 < NC)
            asm volatile("cp.async.wait_group 1;" ::: "memory");
        else
            asm volatile("cp.async.wait_group 0;" ::: "memory");
        __syncthreads();
        if (c + NSTG - 1 < NC) {
            loadc(c + NSTG - 1);
            asm volatile("cp.async.commit_group;" ::: "memory");
        }
        compute(c);
    }

    // ---------------- epilogue ----------------
#pragma unroll
    for (int mg = 0; mg < 4; ++mg) {
        const int r0 = bm + wm + mg * 16 + (lane >> 2);
#pragma unroll
        for (int ng = 0; ng < 8; ++ng) {
            const int cc = bn + wn + ng * 8 + (lane & 3) * 2;
            const float* a = acc[mg][ng];
            if (EPI == 0) {
                float b0 = biasF[cc], b1 = biasF[cc + 1];
                float v0 = a[0] + b0, v1 = a[1] + b1;
                float v2 = a[2] + b0, v3 = a[3] + b1;
                __half h0, l0, h1, l1, h2, l2, h3, l3;
                split1(v0, h0, l0); split1(v1, h1, l1);
                split1(v2, h2, l2); split1(v3, h3, l3);
                *(uint32_t*)(outh + (size_t)r0 * N + cc)       = pack2(h0, h1);
                *(uint32_t*)(outl + (size_t)r0 * N + cc)       = pack2(l0, l1);
                *(uint32_t*)(outh + (size_t)(r0 + 8) * N + cc) = pack2(h2, h3);
                *(uint32_t*)(outl + (size_t)(r0 + 8) * N + cc) = pack2(l2, l3);
            } else if (EPI == 1) {
                *(float2*)(outf + (size_t)r0 * N + cc)       = make_float2(a[0], a[1]);
                *(float2*)(outf + (size_t)(r0 + 8) * N + cc) = make_float2(a[2], a[3]);
            } else {
                size_t o0 = (size_t)r0 * N + cc, o1 = (size_t)(r0 + 8) * N + cc;
                float2 f0 = *(const float2*)(biasF + o0);
                float2 f1 = *(const float2*)(biasF + o1);
                *(float2*)(outf + o0) = make_float2(0.5f * f0.x + 0.5f * a[0],
                                                    0.5f * f0.y + 0.5f * a[1]);
                *(float2*)(outf + o1) = make_float2(0.5f * f1.x + 0.5f * a[2],
                                                    0.5f * f1.y + 0.5f * a[3]);
            }
        }
    }
}

// ---------------- rowwise softmax: fp32 in, fp16 (hi only) out ----------------
__global__ __launch_bounds__(512)
void softmax_h(const float* __restrict__ S, __half* __restrict__ Ph, int cols)
{
    __shared__ float red[16];
    const int tid = threadIdx.x;
    const float4* p = (const float4*)(S + (size_t)blockIdx.x * cols);
    uint2* oh = (uint2*)(Ph + (size_t)blockIdx.x * cols);

    float4 v[4];
    float m = -1e30f;
#pragma unroll
    for (int i = 0; i < 4; ++i) {
        v[i] = p[tid + i * 512];
        m = fmaxf(m, fmaxf(fmaxf(v[i].x, v[i].y), fmaxf(v[i].z, v[i].w)));
    }
#pragma unroll
    for (int o = 16; o; o >>= 1) m = fmaxf(m, __shfl_xor_sync(0xffffffffu, m, o));
    if ((tid & 31) == 0) red[tid >> 5] = m;
    __syncthreads();
    if (tid < 32) {
        float t = (tid < 16) ? red[tid] : -1e30f;
#pragma unroll
        for (int o = 8; o; o >>= 1) t = fmaxf(t, __shfl_xor_sync(0xffffffffu, t, o));
        if (tid == 0) red[0] = t;
    }
    __syncthreads();
    m = red[0];
    __syncthreads();

    float sum = 0.f;
#pragma unroll
    for (int i = 0; i < 4; ++i) {
        v[i].x = __expf(v[i].x - m); v[i].y = __expf(v[i].y - m);
        v[i].z = __expf(v[i].z - m); v[i].w = __expf(v[i].w - m);
        sum += (v[i].x + v[i].y) + (v[i].z + v[i].w);
    }
#pragma unroll
    for (int o = 16; o; o >>= 1) sum += __shfl_xor_sync(0xffffffffu, sum, o);
    if ((tid & 31) == 0) red[tid >> 5] = sum;
    __syncthreads();
    if (tid < 32) {
        float t = (tid < 16) ? red[tid] : 0.f;
#pragma unroll
        for (int o = 8; o; o >>= 1) t += __shfl_xor_sync(0xffffffffu, t, o);
        if (tid == 0) red[0] = t;
    }
    __syncthreads();
    const float inv = 1.0f / red[0];

#pragma unroll
    for (int i = 0; i < 4; ++i) {
        oh[tid + i * 512] = make_uint2(
            pack2(__float2half_rn(v[i].x * inv), __float2half_rn(v[i].y * inv)),
            pack2(__float2half_rn(v[i].z * inv), __float2half_rn(v[i].w * inv)));
    }
}

// ---------------------------------------------------------------------------
extern "C" void kernel_launch(void* const* d_in, const int* in_sizes, int n_in,
                              void* d_out, int out_size)
{
    const float* features = (const float*)d_in[0];
    const float* memoryf  = (const float*)d_in[1];
    const float* Wq       = (const float*)d_in[2];
    const float* bq       = (const float*)d_in[3];
    const float* Wk       = (const float*)d_in[4];
    // bk cancels in softmax (per-row logit constant) -> unused
    float* out            = (float*)d_out;

    __half *fh, *fl, *mh, *ml, *t1h, *t1l, *qh, *ql, *mth, *ph;
    float *s, *cv;
    cudaGetSymbolAddress((void**)&fh, g_fh);   cudaGetSymbolAddress((void**)&fl, g_fl);
    cudaGetSymbolAddress((void**)&mh, g_mh);   cudaGetSymbolAddress((void**)&ml, g_ml);
    cudaGetSymbolAddress((void**)&t1h, g_t1h); cudaGetSymbolAddress((void**)&t1l, g_t1l);
    cudaGetSymbolAddress((void**)&qh, g_qh);   cudaGetSymbolAddress((void**)&ql, g_ql);
    cudaGetSymbolAddress((void**)&mth, g_mth); cudaGetSymbolAddress((void**)&ph, g_ph);
    cudaGetSymbolAddress((void**)&s, g_s);     cudaGetSymbolAddress((void**)&cv, g_c);

    const int SM3 = 2 * 4 * (128 * 80);    // 81920 B : 3-pass, KC32, 2 stages
    const int SM1 = 2 * 2 * (128 * 144);   // 73728 B : 1-pass, KC64, 2 stages
    cudaFuncSetAttribute((const void*)mma_gemm<0,3,2,32>, cudaFuncAttributeMaxDynamicSharedMemorySize, SM3);
    cudaFuncSetAttribute((const void*)mma_gemm<1,3,2,32>, cudaFuncAttributeMaxDynamicSharedMemorySize, SM3);
    cudaFuncSetAttribute((const void*)mma_gemm<2,1,2,64>, cudaFuncAttributeMaxDynamicSharedMemorySize, SM1);

    size_t n4 = (size_t)NR * HD / 4;

    // launch order chosen so the S GEMM is the 6th launch (ncu -s 5 -c 1 window)
    // 1) split features; 2) W-product; 3) bias fold
    split_kernel<<<(unsigned)((n4 + 255) / 256), 256>>>(features, fh, fl, n4);
    wprod_kernel<<<dim3(HD / 16, HD / 16), 256>>>(Wk, Wq, t1h, t1l);
    cvec_kernel<<<HD / 64, 256>>>(bq, Wk, cv);

    // 4) qw = f @ W1 + c  (3-pass, split fp16 out)
    mma_gemm<0,3,2,32><<<dim3(HD / 128, NR / 128), 128, SM3>>>(
        fh, fl, t1h, t1l, cv, nullptr, qh, ql, NR, HD, HD);

    // 5) split memory
    split_kernel<<<(unsigned)((n4 + 255) / 256), 256>>>(memoryf, mh, ml, n4);

    // 6) S = qw @ mem^T  (3-pass, fp32 out)   <- profiled launch
    mma_gemm<1,3,2,32><<<dim3(MR / 128, NR / 128), 128, SM3>>>(
        qh, ql, mh, ml, nullptr, s, nullptr, nullptr, NR, MR, HD);

    // 7) memT (hi only) for the AV GEMM (only AV depends on it)
    transpose_h<<<dim3(MR / 32, HD / 32), 256>>>(memoryf, mth);

    // 8) softmax -> fp16 P (hi only)
    softmax_h<<<NR, 512>>>(s, ph, MR);

    // 9) out = 0.5*features + 0.5*(P @ memT^T)  (1-pass fp16, KC64, 2-stage)
    mma_gemm<2,1,2,64><<<dim3(HD / 128, NR / 128), 128, SM1>>>(
        ph, nullptr, mth, nullptr, features, out, nullptr, nullptr, NR, HD, MR);
}